// round 12
// baseline (speedup 1.0000x reference)
#include <cuda_runtime.h>

// db2 filter constants
#define DL0 (-0.12940952255092145f)
#define DL1 ( 0.22414386804185735f)
#define DL2 ( 0.836516303737469f)
#define DL3 ( 0.48296291314469025f)
#define DH0 (-0.48296291314469025f)
#define DH1 ( 0.836516303737469f)
#define DH2 (-0.22414386804185735f)
#define DH3 (-0.12940952255092145f)
#define RL0 ( 0.48296291314469025f)
#define RL1 ( 0.836516303737469f)
#define RL2 ( 0.22414386804185735f)
#define RL3 (-0.12940952255092145f)
#define RH0 (-0.12940952255092145f)
#define RH1 (-0.22414386804185735f)
#define RH2 ( 0.836516303737469f)
#define RH3 (-0.48296291314469025f)

static constexpr int D        = 512;
static constexpr int WARPS_PB = 8;     // one full row per warp
static constexpr int TPB      = WARPS_PB * 32;
static constexpr unsigned FULL = 0xffffffffu;

// 4 outputs from quad v = x[c..c+3] with halo (m2,m1 | p4,p5) and weights.
__device__ __forceinline__ float4 quad_compute(float m2, float m1, float4 v,
                                               float p4, float p5,
                                               float w0, float w1, float w2)
{
    const float cA0 = fmaf(m2,  DL3, fmaf(m1,  DL2, fmaf(v.x, DL1, v.y * DL0)));
    const float cA1 = fmaf(v.x, DL3, fmaf(v.y, DL2, fmaf(v.z, DL1, v.w * DL0)));
    const float cA2 = fmaf(v.z, DL3, fmaf(v.w, DL2, fmaf(p4,  DL1, p5  * DL0)));

    float cD0 = fmaf(m2,  DH3, fmaf(m1,  DH2, fmaf(v.x, DH1, v.y * DH0)));
    float cD1 = fmaf(v.x, DH3, fmaf(v.y, DH2, fmaf(v.z, DH1, v.w * DH0)));
    float cD2 = fmaf(v.z, DH3, fmaf(v.w, DH2, fmaf(p4,  DH1, p5  * DH0)));
    cD0 *= w0; cD1 *= w1; cD2 *= w2;

    float4 z;
    z.x = fmaf(RL2, cA0, fmaf(RL0, cA1, fmaf(RH2, cD0, RH0 * cD1)));
    z.y = fmaf(RL3, cA0, fmaf(RL1, cA1, fmaf(RH3, cD0, RH1 * cD1)));
    z.z = fmaf(RL2, cA1, fmaf(RL0, cA2, fmaf(RH2, cD1, RH0 * cD2)));
    z.w = fmaf(RL3, cA1, fmaf(RL1, cA2, fmaf(RH3, cD1, RH1 * cD2)));
    z.x = z.x > 0.0f ? z.x : 0.01f * z.x;
    z.y = z.y > 0.0f ? z.y : 0.01f * z.y;
    z.z = z.z > 0.0f ? z.z : 0.01f * z.z;
    z.w = z.w > 0.0f ? z.w : 0.01f * z.w;
    return z;
}

// One warp per 512-float row, owned as FOUR warp-contiguous float4 quads:
//   quad q: x[128q + 4*lane .. +3]   (q = 0..3)
// Every LDG.128/STG.128 instruction covers a contiguous 512B span; all 4
// loads front-batched (MLP_p1=4). All chunk seams are warp-internal (select +
// circular shuffle, uniform flow, zero halo global loads). Row edges are
// register fixups (symmetric extension).
// __launch_bounds__(256, 8): force 32 regs -> 8 CTAs/SM (100% theor. occ).
__global__ __launch_bounds__(TPB, 8)
void wavelet_db2_q4ho_kernel(const float* __restrict__ x,
                             const float* __restrict__ weight,
                             float* __restrict__ out)
{
    const int warp = threadIdx.x >> 5;
    const int lane = threadIdx.x & 31;

    const long long row = (long long)blockIdx.x * WARPS_PB + warp;
    const float* __restrict__ rowp = x + row * D;
    const int co = lane << 2;

    // ---- front-batched, perfectly-coalesced loads ----
    float4 v[4];
#pragma unroll
    for (int q = 0; q < 4; q++)
        v[q] = __ldcs(reinterpret_cast<const float4*>(rowp + (q << 7) + co));

    const int up = (lane + 31) & 31;   // circular lane-1 (lane0 <- lane31)
    const int dn = (lane + 1) & 31;    // circular lane+1 (lane31 <- lane0)

    float* op = out + row * D;

#pragma unroll
    for (int q = 0; q < 4; q++) {
        // left halo: x[cq-2], x[cq-1] from lane-1's v[q].zw;
        // lane0 gets lane31's v[q-1].zw via circular shuffle (seam),
        // except q=0 where it's the symmetric extension.
        const float uz = (q > 0 && lane == 31) ? v[q-1].z : v[q].z;
        const float uw = (q > 0 && lane == 31) ? v[q-1].w : v[q].w;
        float m2 = __shfl_sync(FULL, uz, up);
        float m1 = __shfl_sync(FULL, uw, up);
        if (q == 0 && lane == 0) { m2 = v[0].y; m1 = v[0].x; }   // x[1], x[0]

        // right halo: x[cq+4], x[cq+5] from lane+1's v[q].xy;
        // lane31 gets lane0's v[q+1].xy via circular shuffle (seam),
        // except q=3 where it's the symmetric extension.
        const float ux = (q < 3 && lane == 0) ? v[q+1].x : v[q].x;
        const float uy = (q < 3 && lane == 0) ? v[q+1].y : v[q].y;
        float p4 = __shfl_sync(FULL, ux, dn);
        float p5 = __shfl_sync(FULL, uy, dn);
        if (q == 3 && lane == 31) { p4 = v[3].w; p5 = v[3].z; }  // x[511], x[510]

        // weights: w[k..k+2], k = 64q + 2*lane (even -> aligned float2)
        const int k = (q << 6) + (lane << 1);
        const float2 w01 = __ldg(reinterpret_cast<const float2*>(weight) + (k >> 1));
        const float  w2  = __ldg(weight + k + 2);

        const float4 z = quad_compute(m2, m1, v[q], p4, p5, w01.x, w01.y, w2);
        __stcs(reinterpret_cast<float4*>(op + (q << 7) + co), z);
    }
}

extern "C" void kernel_launch(void* const* d_in, const int* in_sizes, int n_in,
                              void* d_out, int out_size)
{
    const float* x = (const float*)d_in[0];   // (B, 512) fp32
    const float* w = (const float*)d_in[1];   // (2, 257) fp32
    float* out = (float*)d_out;               // (B, 512) fp32

    const int nrows = in_sizes[0] / D;        // 65536
    const int grid  = nrows / WARPS_PB;       // 8192

    wavelet_db2_q4ho_kernel<<<grid, TPB>>>(x, w, out);
}

// round 13
// speedup vs baseline: 1.0007x; 1.0007x over previous
#include <cuda_runtime.h>

// db2 filter constants
#define DL0 (-0.12940952255092145f)
#define DL1 ( 0.22414386804185735f)
#define DL2 ( 0.836516303737469f)
#define DL3 ( 0.48296291314469025f)
#define DH0 (-0.48296291314469025f)
#define DH1 ( 0.836516303737469f)
#define DH2 (-0.22414386804185735f)
#define DH3 (-0.12940952255092145f)
#define RL0 ( 0.48296291314469025f)
#define RL1 ( 0.836516303737469f)
#define RL2 ( 0.22414386804185735f)
#define RL3 (-0.12940952255092145f)
#define RH0 (-0.12940952255092145f)
#define RH1 (-0.22414386804185735f)
#define RH2 ( 0.836516303737469f)
#define RH3 (-0.48296291314469025f)

static constexpr int D        = 512;
static constexpr int WARPS_PB = 8;     // one full row per warp
static constexpr int TPB      = WARPS_PB * 32;
static constexpr unsigned FULL = 0xffffffffu;

// 4 outputs from quad v = x[c..c+3] with halo (m2,m1 | p4,p5) and weights.
__device__ __forceinline__ float4 quad_compute(float m2, float m1, float4 v,
                                               float p4, float p5,
                                               float w0, float w1, float w2)
{
    const float cA0 = fmaf(m2,  DL3, fmaf(m1,  DL2, fmaf(v.x, DL1, v.y * DL0)));
    const float cA1 = fmaf(v.x, DL3, fmaf(v.y, DL2, fmaf(v.z, DL1, v.w * DL0)));
    const float cA2 = fmaf(v.z, DL3, fmaf(v.w, DL2, fmaf(p4,  DL1, p5  * DL0)));

    float cD0 = fmaf(m2,  DH3, fmaf(m1,  DH2, fmaf(v.x, DH1, v.y * DH0)));
    float cD1 = fmaf(v.x, DH3, fmaf(v.y, DH2, fmaf(v.z, DH1, v.w * DH0)));
    float cD2 = fmaf(v.z, DH3, fmaf(v.w, DH2, fmaf(p4,  DH1, p5  * DH0)));
    cD0 *= w0; cD1 *= w1; cD2 *= w2;

    float4 z;
    z.x = fmaf(RL2, cA0, fmaf(RL0, cA1, fmaf(RH2, cD0, RH0 * cD1)));
    z.y = fmaf(RL3, cA0, fmaf(RL1, cA1, fmaf(RH3, cD0, RH1 * cD1)));
    z.z = fmaf(RL2, cA1, fmaf(RL0, cA2, fmaf(RH2, cD1, RH0 * cD2)));
    z.w = fmaf(RL3, cA1, fmaf(RL1, cA2, fmaf(RH3, cD1, RH1 * cD2)));
    z.x = z.x > 0.0f ? z.x : 0.01f * z.x;
    z.y = z.y > 0.0f ? z.y : 0.01f * z.y;
    z.z = z.z > 0.0f ? z.z : 0.01f * z.z;
    z.w = z.w > 0.0f ? z.w : 0.01f * z.w;
    return z;
}

// One warp per 512-float row, owned as FOUR warp-contiguous float4 quads:
//   quad q: x[128q + 4*lane .. +3]   (q = 0..3)
// Every LDG.128/STG.128 instruction covers a contiguous 512B span; all 4
// loads front-batched (MLP_p1=4). All chunk seams are warp-internal (select +
// circular shuffle, uniform flow, zero halo global loads). Row edges are
// register fixups (symmetric extension).
__global__ __launch_bounds__(TPB, 6)
void wavelet_db2_q4_kernel(const float* __restrict__ x,
                           const float* __restrict__ weight,
                           float* __restrict__ out)
{
    const int warp = threadIdx.x >> 5;
    const int lane = threadIdx.x & 31;

    const long long row = (long long)blockIdx.x * WARPS_PB + warp;
    const float* __restrict__ rowp = x + row * D;
    const int co = lane << 2;

    // ---- front-batched, perfectly-coalesced loads ----
    float4 v[4];
#pragma unroll
    for (int q = 0; q < 4; q++)
        v[q] = __ldcs(reinterpret_cast<const float4*>(rowp + (q << 7) + co));

    const int up = (lane + 31) & 31;   // circular lane-1 (lane0 <- lane31)
    const int dn = (lane + 1) & 31;    // circular lane+1 (lane31 <- lane0)

    float* op = out + row * D;

#pragma unroll
    for (int q = 0; q < 4; q++) {
        // left halo: x[cq-2], x[cq-1] from lane-1's v[q].zw;
        // lane0 gets lane31's v[q-1].zw via the circular shuffle (seam),
        // except q=0 where it's the symmetric extension.
        const float uz = (q > 0 && lane == 31) ? v[q-1].z : v[q].z;
        const float uw = (q > 0 && lane == 31) ? v[q-1].w : v[q].w;
        float m2 = __shfl_sync(FULL, uz, up);
        float m1 = __shfl_sync(FULL, uw, up);
        if (q == 0 && lane == 0) { m2 = v[0].y; m1 = v[0].x; }   // x[1], x[0]

        // right halo: x[cq+4], x[cq+5] from lane+1's v[q].xy;
        // lane31 gets lane0's v[q+1].xy via the circular shuffle (seam),
        // except q=3 where it's the symmetric extension.
        const float ux = (q < 3 && lane == 0) ? v[q+1].x : v[q].x;
        const float uy = (q < 3 && lane == 0) ? v[q+1].y : v[q].y;
        float p4 = __shfl_sync(FULL, ux, dn);
        float p5 = __shfl_sync(FULL, uy, dn);
        if (q == 3 && lane == 31) { p4 = v[3].w; p5 = v[3].z; }  // x[511], x[510]

        // weights: w[k..k+2], k = 64q + 2*lane (even -> aligned float2)
        const int k = (q << 6) + (lane << 1);
        const float2 w01 = __ldg(reinterpret_cast<const float2*>(weight) + (k >> 1));
        const float  w2  = __ldg(weight + k + 2);

        const float4 z = quad_compute(m2, m1, v[q], p4, p5, w01.x, w01.y, w2);
        __stcs(reinterpret_cast<float4*>(op + (q << 7) + co), z);
    }
}

extern "C" void kernel_launch(void* const* d_in, const int* in_sizes, int n_in,
                              void* d_out, int out_size)
{
    const float* x = (const float*)d_in[0];   // (B, 512) fp32
    const float* w = (const float*)d_in[1];   // (2, 257) fp32
    float* out = (float*)d_out;               // (B, 512) fp32

    const int nrows = in_sizes[0] / D;        // 65536
    const int grid  = nrows / WARPS_PB;       // 8192

    wavelet_db2_q4_kernel<<<grid, TPB>>>(x, w, out);
}